// round 1
// baseline (speedup 1.0000x reference)
#include <cuda_runtime.h>
#include <cuda_bf16.h>
#include <math.h>

// Problem constants
#define Bq    8
#define NINST 16384
#define Dd    512
#define Cc    2
#define Gg    8
#define Kk    4
#define BUF   1024
#define DA    128
#define NN    1032            // B + BUF
#define Mm    2048            // NINST / G
#define RR    131072          // B * NINST
#define NGRP  64              // B * G
#define DH    256             // D/2

// -------- scratch (device globals; allocation-free rule) --------
__device__ float g_mid[(size_t)RR * Dd];   // 268 MB
__device__ float g_a[RR];
__device__ float g_af[NGRP * Dd];
__device__ float g_a2[NGRP];
__device__ float g_bag[Bq * Dd];
__device__ float g_xc[NN * Dd];
__device__ float g_xn[NN * DH];
__device__ int   g_idx[NN * Kk];
__device__ float g_h[NN * Dd];
__device__ float g_m1[NN * Dd];
__device__ float g_h1[NN * Dd];

__device__ __forceinline__ float sigmoidf_(float x) { return 1.f / (1.f + expf(-x)); }

// ================= K1: mid = relu(X @ Wdr + bdr) =================
// 128x128 tile, BK=8, 256 threads, 8x8 per thread
__global__ void k_gemm_mid(const float* __restrict__ X, const float* __restrict__ W,
                           const float* __restrict__ bias)
{
    __shared__ float As[8][128];
    __shared__ float Bs[8][128];
    const int bm = blockIdx.y * 128;
    const int bn = blockIdx.x * 128;
    const int tid = threadIdx.x;
    const int tx = tid & 15, ty = tid >> 4;

    float acc[8][8];
#pragma unroll
    for (int i = 0; i < 8; i++)
#pragma unroll
        for (int j = 0; j < 8; j++) acc[i][j] = 0.f;

    const int arow = tid >> 1;
    const int acol = (tid & 1) * 4;
    const int brow = tid >> 5;
    const int bcol = (tid & 31) * 4;

    for (int k0 = 0; k0 < Dd; k0 += 8) {
        float4 av = *(const float4*)&X[(size_t)(bm + arow) * Dd + k0 + acol];
        As[acol + 0][arow] = av.x; As[acol + 1][arow] = av.y;
        As[acol + 2][arow] = av.z; As[acol + 3][arow] = av.w;
        *(float4*)&Bs[brow][bcol] = *(const float4*)&W[(size_t)(k0 + brow) * Dd + bn + bcol];
        __syncthreads();
#pragma unroll
        for (int k = 0; k < 8; k++) {
            float a[8], b[8];
            *(float4*)&a[0] = *(float4*)&As[k][ty * 8];
            *(float4*)&a[4] = *(float4*)&As[k][ty * 8 + 4];
            *(float4*)&b[0] = *(float4*)&Bs[k][tx * 8];
            *(float4*)&b[4] = *(float4*)&Bs[k][tx * 8 + 4];
#pragma unroll
            for (int i = 0; i < 8; i++)
#pragma unroll
                for (int j = 0; j < 8; j++) acc[i][j] += a[i] * b[j];
        }
        __syncthreads();
    }
#pragma unroll
    for (int i = 0; i < 8; i++) {
        const int row = bm + ty * 8 + i;
#pragma unroll
        for (int j = 0; j < 8; j++) {
            const int col = bn + tx * 8 + j;
            float v = acc[i][j] + bias[col];
            g_mid[(size_t)row * Dd + col] = v > 0.f ? v : 0.f;
        }
    }
}

// ================= K2: attention scores a[r] =================
// 32 rows per block, 256 threads; V/U projections (D->DA) + gated reduce
__global__ void k_score(const float* __restrict__ Wv, const float* __restrict__ bv,
                        const float* __restrict__ Wu, const float* __restrict__ bu,
                        const float* __restrict__ Ww, const float* __restrict__ bw)
{
    __shared__ float midS[32][32];
    __shared__ float WvS[32][DA];
    __shared__ float WuS[32][DA];
    const int tid = threadIdx.x;
    const int lane = tid & 31, ty = tid >> 5;
    const int rowBase = blockIdx.x * 32;

    float v[4][4], u[4][4];
#pragma unroll
    for (int i = 0; i < 4; i++)
#pragma unroll
        for (int j = 0; j < 4; j++) { v[i][j] = 0.f; u[i][j] = 0.f; }

    for (int k0 = 0; k0 < Dd; k0 += 32) {
        for (int i = tid; i < 32 * 32; i += 256) {
            int r = i >> 5, c = i & 31;
            midS[r][c] = g_mid[(size_t)(rowBase + r) * Dd + k0 + c];
        }
        for (int i = tid; i < 32 * DA; i += 256) {
            int r = i >> 7, c = i & 127;
            WvS[r][c] = Wv[(size_t)(k0 + r) * DA + c];
            WuS[r][c] = Wu[(size_t)(k0 + r) * DA + c];
        }
        __syncthreads();
#pragma unroll 4
        for (int k = 0; k < 32; k++) {
            float wv[4], wu[4];
#pragma unroll
            for (int jj = 0; jj < 4; jj++) {
                wv[jj] = WvS[k][lane + 32 * jj];
                wu[jj] = WuS[k][lane + 32 * jj];
            }
#pragma unroll
            for (int ri = 0; ri < 4; ri++) {
                float m = midS[ty * 4 + ri][k];
#pragma unroll
                for (int jj = 0; jj < 4; jj++) {
                    v[ri][jj] += m * wv[jj];
                    u[ri][jj] += m * wu[jj];
                }
            }
        }
        __syncthreads();
    }
#pragma unroll
    for (int ri = 0; ri < 4; ri++) {
        float s = 0.f;
#pragma unroll
        for (int jj = 0; jj < 4; jj++) {
            int j = lane + 32 * jj;
            float vv = tanhf(v[ri][jj] + bv[j]);
            float uu = sigmoidf_(u[ri][jj] + bu[j]);
            s += vv * uu * Ww[j];
        }
#pragma unroll
        for (int o = 16; o > 0; o >>= 1) s += __shfl_xor_sync(0xffffffffu, s, o);
        if (lane == 0) g_a[rowBase + ty * 4 + ri] = s + bw[0];
    }
}

// ================= K3: softmax over each group of 2048 =================
__global__ void k_softmax()
{
    __shared__ float red[256];
    float* p = g_a + (size_t)blockIdx.x * Mm;
    const int tid = threadIdx.x;
    float mx = -INFINITY;
    for (int i = tid; i < Mm; i += 256) mx = fmaxf(mx, p[i]);
    red[tid] = mx; __syncthreads();
    for (int s = 128; s > 0; s >>= 1) { if (tid < s) red[tid] = fmaxf(red[tid], red[tid + s]); __syncthreads(); }
    mx = red[0]; __syncthreads();
    float sum = 0.f;
    for (int i = tid; i < Mm; i += 256) { float e = expf(p[i] - mx); p[i] = e; sum += e; }
    red[tid] = sum; __syncthreads();
    for (int s = 128; s > 0; s >>= 1) { if (tid < s) red[tid] += red[tid + s]; __syncthreads(); }
    float inv = 1.f / red[0];
    for (int i = tid; i < Mm; i += 256) p[i] *= inv;
}

// ================= K4: af[g][d] = sum_m A[m]*mid[m][d] =================
__global__ void k_af()
{
    __shared__ float Asm[Mm];
    const int g = blockIdx.x;
    const int d = threadIdx.x;  // 512 threads
    const float* mb = g_mid + (size_t)g * Mm * Dd;
    for (int i = d; i < Mm; i += 512) Asm[i] = g_a[(size_t)g * Mm + i];
    __syncthreads();
    float a0 = 0, a1 = 0, a2 = 0, a3 = 0;
    for (int m = 0; m < Mm; m += 4) {
        a0 += Asm[m + 0] * mb[(size_t)(m + 0) * Dd + d];
        a1 += Asm[m + 1] * mb[(size_t)(m + 1) * Dd + d];
        a2 += Asm[m + 2] * mb[(size_t)(m + 2) * Dd + d];
        a3 += Asm[m + 3] * mb[(size_t)(m + 3) * Dd + d];
    }
    g_af[g * Dd + d] = (a0 + a1) + (a2 + a3);
}

// ================= K5: sub_preds_cat -> out[16..143] =================
__global__ void k_subpreds(const float* __restrict__ Wsc, const float* __restrict__ bsc,
                           float* __restrict__ out)
{
    const int t = threadIdx.x;          // 128 threads
    const int c = t & 1;
    const int rowcat = t >> 1;          // g*8 + b
    const int g = rowcat >> 3, b = rowcat & 7;
    const float* af = g_af + (size_t)(b * Gg + g) * Dd;
    float acc = bsc[c];
    for (int d = 0; d < Dd; d++) acc += af[d] * Wsc[d * Cc + c];
    out[16 + rowcat * Cc + c] = acc;
}

// ================= K6: second attention scores a2 =================
__global__ void k_a2(const float* __restrict__ Wv2, const float* __restrict__ bv2,
                     const float* __restrict__ Wu2, const float* __restrict__ bu2,
                     const float* __restrict__ Ww2, const float* __restrict__ bw2)
{
    __shared__ float red[DA];
    const int row = blockIdx.x;         // 64 rows of af
    const int j = threadIdx.x;          // 128 threads
    const float* af = g_af + (size_t)row * Dd;
    float dv = bv2[j], du = bu2[j];
    for (int d = 0; d < Dd; d++) {
        float a = af[d];
        dv += a * Wv2[d * DA + j];
        du += a * Wu2[d * DA + j];
    }
    red[j] = tanhf(dv) * sigmoidf_(du) * Ww2[j];
    __syncthreads();
    for (int s = 64; s > 0; s >>= 1) { if (j < s) red[j] += red[j + s]; __syncthreads(); }
    if (j == 0) g_a2[row] = red[0] + bw2[0];
}

// ================= K7: softmax over G + bag_feat =================
__global__ void k_bag()
{
    const int b = blockIdx.x;           // 8 blocks
    const int d = threadIdx.x;          // 512 threads
    float av[Gg];
    float mx = -INFINITY;
#pragma unroll
    for (int g = 0; g < Gg; g++) { av[g] = g_a2[b * Gg + g]; mx = fmaxf(mx, av[g]); }
    float s = 0.f;
#pragma unroll
    for (int g = 0; g < Gg; g++) { av[g] = expf(av[g] - mx); s += av[g]; }
    float inv = 1.f / s;
    float acc = 0.f;
#pragma unroll
    for (int g = 0; g < Gg; g++) acc += av[g] * inv * g_af[(size_t)(b * Gg + g) * Dd + d];
    g_bag[b * Dd + d] = acc;
}

// ================= K8: bag_pred -> out[0..15] =================
__global__ void k_bagpred(const float* __restrict__ Wbc, const float* __restrict__ bbc,
                          float* __restrict__ out)
{
    const int t = threadIdx.x;  // 16
    const int b = t >> 1, c = t & 1;
    float acc = bbc[c];
    for (int d = 0; d < Dd; d++) acc += g_bag[b * Dd + d] * Wbc[d * Cc + c];
    out[t] = acc;
}

// ================= K9: x_concat =================
__global__ void k_xc(const float* __restrict__ rehearsal)
{
    const int i = blockIdx.x;   // 1032
    for (int d = threadIdx.x; d < Dd; d += 256)
        g_xc[(size_t)i * Dd + d] = (i < Bq) ? g_bag[i * Dd + d] : rehearsal[(size_t)(i - Bq) * Dd + d];
}

// ================= K10: _x = lrelu(xc @ Wf + bf); xn = normalize =================
__global__ void k_feat(const float* __restrict__ Wf, const float* __restrict__ bf)
{
    __shared__ float xs[Dd];
    __shared__ float red[DH];
    const int i = blockIdx.x;   // 1032
    const int j = threadIdx.x;  // 256
    for (int d = j; d < Dd; d += DH) xs[d] = g_xc[(size_t)i * Dd + d];
    __syncthreads();
    float f = bf[j];
    for (int d = 0; d < Dd; d++) f += xs[d] * Wf[d * DH + j];
    f = (f >= 0.f) ? f : 0.01f * f;
    red[j] = f * f;
    __syncthreads();
    for (int s = 128; s > 0; s >>= 1) { if (j < s) red[j] += red[j + s]; __syncthreads(); }
    g_xn[(size_t)i * DH + j] = f / (sqrtf(red[0]) + 1e-12f);
}

// ================= K11: sim row + top-4 (JAX tie rule: lower index first) ====
__device__ __forceinline__ void topk_insert(float* bv, int* bi, float val, int id)
{
#pragma unroll
    for (int s = 0; s < Kk; s++) {
        if (val > bv[s] || (val == bv[s] && id < bi[s])) {
            for (int t = Kk - 1; t > s; t--) { bv[t] = bv[t - 1]; bi[t] = bi[t - 1]; }
            bv[s] = val; bi[s] = id;
            return;
        }
    }
}

__global__ void k_topk()
{
    __shared__ float xs[DH];
    __shared__ float sv[8][Kk];
    __shared__ int   si[8][Kk];
    const int i = blockIdx.x;           // 1032
    const int tid = threadIdx.x;        // 256 = 8 warps
    const int lane = tid & 31, w = tid >> 5;
    xs[tid] = g_xn[(size_t)i * DH + tid];
    __syncthreads();

    float bv[Kk]; int bi[Kk];
#pragma unroll
    for (int t = 0; t < Kk; t++) { bv[t] = -INFINITY; bi[t] = 0x7fffffff; }

    for (int j = w; j < NN; j += 8) {
        const float* xj = g_xn + (size_t)j * DH;
        float s = 0.f;
#pragma unroll
        for (int t = 0; t < 8; t++) s += xs[lane + 32 * t] * xj[lane + 32 * t];
#pragma unroll
        for (int o = 16; o > 0; o >>= 1) s += __shfl_xor_sync(0xffffffffu, s, o);
        if (lane == 0) topk_insert(bv, bi, s, j);
    }
    if (lane == 0) {
#pragma unroll
        for (int t = 0; t < Kk; t++) { sv[w][t] = bv[t]; si[w][t] = bi[t]; }
    }
    __syncthreads();
    if (tid == 0) {
        float fv[Kk]; int fi[Kk];
#pragma unroll
        for (int t = 0; t < Kk; t++) { fv[t] = -INFINITY; fi[t] = 0x7fffffff; }
        for (int w2 = 0; w2 < 8; w2++)
            for (int t = 0; t < Kk; t++) topk_insert(fv, fi, sv[w2][t], si[w2][t]);
        for (int t = 0; t < Kk; t++) g_idx[i * Kk + t] = fi[t];
    }
}

// ================= K12: h = padded + edge_attr =================
__global__ void k_h()
{
    const int i = blockIdx.x;   // 1032
    const int d = threadIdx.x;  // 512
    const int i0 = g_idx[i * Kk + 0], i1 = g_idx[i * Kk + 1];
    const int i2 = g_idx[i * Kk + 2], i3 = g_idx[i * Kk + 3];
    float e = 0.25f * (g_xc[(size_t)i0 * Dd + d] + g_xc[(size_t)i1 * Dd + d] +
                       g_xc[(size_t)i2 * Dd + d] + g_xc[(size_t)i3 * Dd + d]);
    float pad = (i < Bq) ? g_bag[i * Dd + d] : 0.f;
    g_h[(size_t)i * Dd + d] = pad + e;
}

// ================= K13: m1 = mean(h[idx]) =================
__global__ void k_m1()
{
    const int i = blockIdx.x;
    const int d = threadIdx.x;
    const int i0 = g_idx[i * Kk + 0], i1 = g_idx[i * Kk + 1];
    const int i2 = g_idx[i * Kk + 2], i3 = g_idx[i * Kk + 3];
    g_m1[(size_t)i * Dd + d] = 0.25f * (g_h[(size_t)i0 * Dd + d] + g_h[(size_t)i1 * Dd + d] +
                                        g_h[(size_t)i2 * Dd + d] + g_h[(size_t)i3 * Dd + d]);
}

// ================= K14: h1 = relu(m1@Wg1 + h@Wg1s + bg1), 8 rows/block ======
__global__ void k_h1(const float* __restrict__ Wg1, const float* __restrict__ Wg1s,
                     const float* __restrict__ bg1)
{
    __shared__ float m1S[8][Dd];
    __shared__ float hS[8][Dd];
    const int rb = blockIdx.x * 8;      // 129 blocks
    const int j = threadIdx.x;          // 512
    for (int t = j; t < 8 * Dd; t += Dd) {
        int r = t >> 9, d = t & 511;
        m1S[r][d] = g_m1[(size_t)(rb + r) * Dd + d];
        hS[r][d]  = g_h[(size_t)(rb + r) * Dd + d];
    }
    __syncthreads();
    float acc[8];
    const float b0 = bg1[j];
#pragma unroll
    for (int r = 0; r < 8; r++) acc[r] = b0;
    for (int d = 0; d < Dd; d++) {
        float w1 = Wg1[(size_t)d * Dd + j];
        float ws = Wg1s[(size_t)d * Dd + j];
#pragma unroll
        for (int r = 0; r < 8; r++) acc[r] += m1S[r][d] * w1 + hS[r][d] * ws;
    }
#pragma unroll
    for (int r = 0; r < 8; r++)
        g_h1[(size_t)(rb + r) * Dd + j] = acc[r] > 0.f ? acc[r] : 0.f;
}

// ================= K15: logits_graph -> out[144..159] =================
__global__ void k_logits(const float* __restrict__ Wg2, const float* __restrict__ Wg2s,
                         const float* __restrict__ bg2, float* __restrict__ out)
{
    __shared__ float r0[Dd];
    __shared__ float r1[Dd];
    const int i = blockIdx.x;   // 8
    const int d = threadIdx.x;  // 512
    const int i0 = g_idx[i * Kk + 0], i1 = g_idx[i * Kk + 1];
    const int i2 = g_idx[i * Kk + 2], i3 = g_idx[i * Kk + 3];
    float m2 = 0.25f * (g_h1[(size_t)i0 * Dd + d] + g_h1[(size_t)i1 * Dd + d] +
                        g_h1[(size_t)i2 * Dd + d] + g_h1[(size_t)i3 * Dd + d]);
    float hv = g_h1[(size_t)i * Dd + d];
    r0[d] = m2 * Wg2[d * Cc + 0] + hv * Wg2s[d * Cc + 0];
    r1[d] = m2 * Wg2[d * Cc + 1] + hv * Wg2s[d * Cc + 1];
    __syncthreads();
    for (int s = 256; s > 0; s >>= 1) {
        if (d < s) { r0[d] += r0[d + s]; r1[d] += r1[d + s]; }
        __syncthreads();
    }
    if (d == 0) {
        out[144 + i * Cc + 0] = r0[0] + bg2[0];
        out[144 + i * Cc + 1] = r1[0] + bg2[1];
    }
}

// ======================= launch =======================
extern "C" void kernel_launch(void* const* d_in, const int* in_sizes, int n_in,
                              void* d_out, int out_size)
{
    const float* x    = (const float*)d_in[0];
    const float* reh  = (const float*)d_in[1];
    const float* Wdr  = (const float*)d_in[2];
    const float* bdr  = (const float*)d_in[3];
    const float* Wv1  = (const float*)d_in[4];
    const float* bv1  = (const float*)d_in[5];
    const float* Wu1  = (const float*)d_in[6];
    const float* bu1  = (const float*)d_in[7];
    const float* Ww1  = (const float*)d_in[8];
    const float* bw1  = (const float*)d_in[9];
    const float* Wsc  = (const float*)d_in[10];
    const float* bsc  = (const float*)d_in[11];
    const float* Wv2  = (const float*)d_in[12];
    const float* bv2  = (const float*)d_in[13];
    const float* Wu2  = (const float*)d_in[14];
    const float* bu2  = (const float*)d_in[15];
    const float* Ww2  = (const float*)d_in[16];
    const float* bw2  = (const float*)d_in[17];
    const float* Wbc  = (const float*)d_in[18];
    const float* bbc  = (const float*)d_in[19];
    const float* Wf   = (const float*)d_in[20];
    const float* bf   = (const float*)d_in[21];
    const float* Wg1  = (const float*)d_in[22];
    const float* Wg1s = (const float*)d_in[23];
    const float* bg1  = (const float*)d_in[24];
    const float* Wg2  = (const float*)d_in[25];
    const float* Wg2s = (const float*)d_in[26];
    const float* bg2  = (const float*)d_in[27];
    float* out = (float*)d_out;

    k_gemm_mid<<<dim3(Dd / 128, RR / 128), 256>>>(x, Wdr, bdr);
    k_score<<<RR / 32, 256>>>(Wv1, bv1, Wu1, bu1, Ww1, bw1);
    k_softmax<<<NGRP, 256>>>();
    k_af<<<NGRP, 512>>>();
    k_subpreds<<<1, 128>>>(Wsc, bsc, out);
    k_a2<<<NGRP, DA>>>(Wv2, bv2, Wu2, bu2, Ww2, bw2);
    k_bag<<<Bq, Dd>>>();
    k_bagpred<<<1, 16>>>(Wbc, bbc, out);
    k_xc<<<NN, 256>>>(reh);
    k_feat<<<NN, DH>>>(Wf, bf);
    k_topk<<<NN, 256>>>();
    k_h<<<NN, Dd>>>();
    k_m1<<<NN, Dd>>>();
    k_h1<<<NN / 8, Dd>>>(Wg1, Wg1s, bg1);
    k_logits<<<Bq, Dd>>>(Wg2, Wg2s, bg2, out);
}

// round 3
// speedup vs baseline: 2.3266x; 2.3266x over previous
#include <cuda_runtime.h>
#include <cuda_bf16.h>
#include <math.h>
#include <stdint.h>

// Problem constants
#define Bq    8
#define NINST 16384
#define Dd    512
#define Cc    2
#define Gg    8
#define Kk    4
#define BUF   1024
#define DA    128
#define NN    1032
#define Mm    2048
#define RR    131072
#define NGRP  64
#define DH    256

#define BK 32
#define SA 40    // A smem row stride (bf16 elems)
#define SB 136   // B smem row stride (bf16 elems)

// -------- scratch (device globals) --------
__device__ __align__(16) unsigned short g_midh[(size_t)RR * Dd];   // 134 MB bf16 hi
__device__ __align__(16) unsigned short g_midl[(size_t)RR * Dd];   // 134 MB bf16 lo
__device__ __align__(16) unsigned short g_Bdrh[512 * 512];
__device__ __align__(16) unsigned short g_Bdrl[512 * 512];
__device__ __align__(16) unsigned short g_Bvuh[512 * 256];
__device__ __align__(16) unsigned short g_Bvul[512 * 256];
__device__ float g_vu[(size_t)RR * 256];                            // 134 MB
__device__ float g_a[RR];
__device__ float g_afp[NGRP * 8 * Dd];
__device__ float g_af[NGRP * Dd];
__device__ float g_a2[NGRP];
__device__ float g_bag[Bq * Dd];
__device__ float g_xc[NN * Dd];
__device__ float g_xn[NN * DH];
__device__ int   g_idx[NN * Kk];
__device__ float g_h[NN * Dd];
__device__ float g_m1[NN * Dd];
__device__ float g_h1[NN * Dd];

__device__ __forceinline__ float sigmoidf_(float x) { return 1.f / (1.f + expf(-x)); }

__device__ __forceinline__ uint32_t smem_u32(const void* p) {
    uint32_t a;
    asm("{ .reg .u64 t; cvta.to.shared.u64 t, %1; cvt.u32.u64 %0, t; }" : "=r"(a) : "l"(p));
    return a;
}
__device__ __forceinline__ void ldsm_x4(uint32_t* r, uint32_t addr) {
    asm volatile("ldmatrix.sync.aligned.m8n8.x4.shared.b16 {%0,%1,%2,%3}, [%4];"
        : "=r"(r[0]), "=r"(r[1]), "=r"(r[2]), "=r"(r[3]) : "r"(addr));
}
__device__ __forceinline__ void ldsm_x4t(uint32_t* r, uint32_t addr) {
    asm volatile("ldmatrix.sync.aligned.m8n8.x4.trans.shared.b16 {%0,%1,%2,%3}, [%4];"
        : "=r"(r[0]), "=r"(r[1]), "=r"(r[2]), "=r"(r[3]) : "r"(addr));
}
__device__ __forceinline__ void mma16816(float* c, const uint32_t* a, uint32_t b0, uint32_t b1) {
    asm volatile("mma.sync.aligned.m16n8k16.row.col.f32.bf16.bf16.f32 "
        "{%0,%1,%2,%3}, {%4,%5,%6,%7}, {%8,%9}, {%0,%1,%2,%3};"
        : "+f"(c[0]), "+f"(c[1]), "+f"(c[2]), "+f"(c[3])
        : "r"(a[0]), "r"(a[1]), "r"(a[2]), "r"(a[3]), "r"(b0), "r"(b1));
}
__device__ __forceinline__ void split_bf16(float v, unsigned short& h, unsigned short& l) {
    h = __bfloat16_as_ushort(__float2bfloat16(v));
    float r = v - __uint_as_float((uint32_t)h << 16);
    l = __bfloat16_as_ushort(__float2bfloat16(r));
}
__device__ __forceinline__ void mma_block(float c[4][4][4], uint32_t a[4][4],
                                          uint32_t b0[4], uint32_t b1[4]) {
#pragma unroll
    for (int mi = 0; mi < 4; mi++) {
        mma16816(c[mi][0], a[mi], b0[0], b0[1]);
        mma16816(c[mi][1], a[mi], b0[2], b0[3]);
        mma16816(c[mi][2], a[mi], b1[0], b1[1]);
        mma16816(c[mi][3], a[mi], b1[2], b1[3]);
    }
}
__device__ __forceinline__ void load_afrag(uint32_t a[4][4], uint32_t base) {
#pragma unroll
    for (int mi = 0; mi < 4; mi++) ldsm_x4(a[mi], base + mi * 16 * SA * 2);
}

// ---------------- prep: split weights to bf16 hi/lo (row-major) -----------
__global__ void k_prepWdr(const float* __restrict__ W) {
    int t = blockIdx.x * 256 + threadIdx.x;      // 262144
    unsigned short h, l; split_bf16(W[t], h, l);
    g_Bdrh[t] = h; g_Bdrl[t] = l;
}
__global__ void k_prepWvu(const float* __restrict__ Wv, const float* __restrict__ Wu) {
    int t = blockIdx.x * 256 + threadIdx.x;      // 131072
    int k = t >> 8, n = t & 255;
    float v = (n < 128) ? Wv[k * 128 + n] : Wu[k * 128 + (n - 128)];
    unsigned short h, l; split_bf16(v, h, l);
    g_Bvuh[t] = h; g_Bvul[t] = l;
}

// ---------------- K1: mid = relu(X @ Wdr + bdr)  (mma.sync) ----------------
__global__ __launch_bounds__(256, 2) void k_gemm1(const float* __restrict__ X,
                                                  const float* __restrict__ bdr)
{
    __shared__ unsigned short Ah[128 * SA], Al[128 * SA], Bh[BK * SB], Bl[BK * SB];
    const int tid = threadIdx.x, lane = tid & 31, wid = tid >> 5;
    const int bm = blockIdx.y * 128, bn = blockIdx.x * 128;
    const int mw = wid >> 2, nw = wid & 3;

    float c[4][4][4];
#pragma unroll
    for (int i = 0; i < 4; i++)
#pragma unroll
        for (int j = 0; j < 4; j++)
#pragma unroll
            for (int q = 0; q < 4; q++) c[i][j][q] = 0.f;

    const uint32_t aHb = smem_u32(Ah), aLb = smem_u32(Al);
    const uint32_t bHb = smem_u32(Bh), bLb = smem_u32(Bl);
    const int lrow = lane & 7, lmat = lane >> 3;
    const uint32_t aOff = ((64 * mw + 8 * (lmat & 1) + lrow) * SA + 8 * (lmat >> 1)) * 2;
    const uint32_t bOff = ((8 * (lmat & 1) + lrow) * SB + 32 * nw + 8 * (lmat >> 1)) * 2;

    for (int kc = 0; kc < 16; kc++) {
        const int k0 = kc * BK;
#pragma unroll
        for (int it = 0; it < 4; it++) {
            int i = it * 256 + tid;
            int row = i >> 3, c4 = (i & 7) << 2;
            float4 xv = *(const float4*)&X[(size_t)(bm + row) * 512 + k0 + c4];
            unsigned short h0, l0, h1, l1, h2, l2, h3, l3;
            split_bf16(xv.x, h0, l0); split_bf16(xv.y, h1, l1);
            split_bf16(xv.z, h2, l2); split_bf16(xv.w, h3, l3);
            uint2 ph = make_uint2((uint32_t)h0 | ((uint32_t)h1 << 16), (uint32_t)h2 | ((uint32_t)h3 << 16));
            uint2 pl = make_uint2((uint32_t)l0 | ((uint32_t)l1 << 16), (uint32_t)l2 | ((uint32_t)l3 << 16));
            *(uint2*)&Ah[row * SA + c4] = ph;
            *(uint2*)&Al[row * SA + c4] = pl;
        }
#pragma unroll
        for (int it = 0; it < 2; it++) {
            int i = it * 256 + tid;
            int row = i >> 4, c8 = (i & 15) << 3;
            *(uint4*)&Bh[row * SB + c8] = *(const uint4*)&g_Bdrh[(size_t)(k0 + row) * 512 + bn + c8];
            *(uint4*)&Bl[row * SB + c8] = *(const uint4*)&g_Bdrl[(size_t)(k0 + row) * 512 + bn + c8];
        }
        __syncthreads();
#pragma unroll
        for (int k16 = 0; k16 < 2; k16++) {
            const uint32_t ao = aOff + k16 * 32;           // 16 k-cols * 2B
            const uint32_t bo = bOff + k16 * 16 * SB * 2;
            uint32_t a[4][4], b0[4], b1[4];
            load_afrag(a, aHb + ao);
            ldsm_x4t(b0, bHb + bo); ldsm_x4t(b1, bHb + bo + 32);
            mma_block(c, a, b0, b1);          // H*H
            load_afrag(a, aLb + ao);
            mma_block(c, a, b0, b1);          // L*H
            load_afrag(a, aHb + ao);
            ldsm_x4t(b0, bLb + bo); ldsm_x4t(b1, bLb + bo + 32);
            mma_block(c, a, b0, b1);          // H*L
        }
        __syncthreads();
    }

    const int gr = lane >> 2, tg = lane & 3;
#pragma unroll
    for (int mi = 0; mi < 4; mi++) {
        const int r0 = bm + 64 * mw + 16 * mi + gr;
#pragma unroll
        for (int n8 = 0; n8 < 4; n8++) {
            const int col = bn + 32 * nw + 8 * n8 + 2 * tg;
            const float bb0 = __ldg(bdr + col), bb1 = __ldg(bdr + col + 1);
#pragma unroll
            for (int half = 0; half < 2; half++) {
                const int row = r0 + 8 * half;
                float v0 = fmaxf(c[mi][n8][2 * half]     + bb0, 0.f);
                float v1 = fmaxf(c[mi][n8][2 * half + 1] + bb1, 0.f);
                unsigned short h0, l0, h1, l1;
                split_bf16(v0, h0, l0); split_bf16(v1, h1, l1);
                size_t o = (size_t)row * 512 + col;
                *(uint32_t*)&g_midh[o] = (uint32_t)h0 | ((uint32_t)h1 << 16);
                *(uint32_t*)&g_midl[o] = (uint32_t)l0 | ((uint32_t)l1 << 16);
            }
        }
    }
}

// ---------------- K2: VU = mid @ [Wv1|Wu1], fused activation ----------------
__global__ __launch_bounds__(256, 2) void k_gemm2(const float* __restrict__ bv,
                                                  const float* __restrict__ bu,
                                                  const float* __restrict__ Ww)
{
    __shared__ unsigned short Ah[128 * SA], Al[128 * SA], Bh[BK * SB], Bl[BK * SB];
    const int tid = threadIdx.x, lane = tid & 31, wid = tid >> 5;
    const int bm = blockIdx.y * 128, bn = blockIdx.x * 128;
    const int mw = wid >> 2, nw = wid & 3;

    float c[4][4][4];
#pragma unroll
    for (int i = 0; i < 4; i++)
#pragma unroll
        for (int j = 0; j < 4; j++)
#pragma unroll
            for (int q = 0; q < 4; q++) c[i][j][q] = 0.f;

    const uint32_t aHb = smem_u32(Ah), aLb = smem_u32(Al);
    const uint32_t bHb = smem_u32(Bh), bLb = smem_u32(Bl);
    const int lrow = lane & 7, lmat = lane >> 3;
    const uint32_t aOff = ((64 * mw + 8 * (lmat & 1) + lrow) * SA + 8 * (lmat >> 1)) * 2;
    const uint32_t bOff = ((8 * (lmat & 1) + lrow) * SB + 32 * nw + 8 * (lmat >> 1)) * 2;

    for (int kc = 0; kc < 16; kc++) {
        const int k0 = kc * BK;
#pragma unroll
        for (int it = 0; it < 2; it++) {
            int i = it * 256 + tid;          // 512 uint4 = 4096 bf16
            int row = i >> 2, c8 = (i & 3) << 3;
            size_t src = (size_t)(bm + row) * 512 + k0 + c8;
            *(uint4*)&Ah[row * SA + c8] = *(const uint4*)&g_midh[src];
            *(uint4*)&Al[row * SA + c8] = *(const uint4*)&g_midl[src];
        }
#pragma unroll
        for (int it = 0; it < 2; it++) {
            int i = it * 256 + tid;
            int row = i >> 4, c8 = (i & 15) << 3;
            *(uint4*)&Bh[row * SB + c8] = *(const uint4*)&g_Bvuh[(size_t)(k0 + row) * 256 + bn + c8];
            *(uint4*)&Bl[row * SB + c8] = *(const uint4*)&g_Bvul[(size_t)(k0 + row) * 256 + bn + c8];
        }
        __syncthreads();
#pragma unroll
        for (int k16 = 0; k16 < 2; k16++) {
            const uint32_t ao = aOff + k16 * 32;
            const uint32_t bo = bOff + k16 * 16 * SB * 2;
            uint32_t a[4][4], b0[4], b1[4];
            load_afrag(a, aHb + ao);
            ldsm_x4t(b0, bHb + bo); ldsm_x4t(b1, bHb + bo + 32);
            mma_block(c, a, b0, b1);
            load_afrag(a, aLb + ao);
            mma_block(c, a, b0, b1);
            load_afrag(a, aHb + ao);
            ldsm_x4t(b0, bLb + bo); ldsm_x4t(b1, bLb + bo + 32);
            mma_block(c, a, b0, b1);
        }
        __syncthreads();
    }

    const int gr = lane >> 2, tg = lane & 3;
#pragma unroll
    for (int mi = 0; mi < 4; mi++) {
        const int r0 = bm + 64 * mw + 16 * mi + gr;
#pragma unroll
        for (int n8 = 0; n8 < 4; n8++) {
            const int col = bn + 32 * nw + 8 * n8 + 2 * tg;
#pragma unroll
            for (int half = 0; half < 2; half++) {
                const int row = r0 + 8 * half;
                float v0 = c[mi][n8][2 * half], v1 = c[mi][n8][2 * half + 1];
                float2 o;
                if (col < 128) {
                    o.x = tanhf(v0 + __ldg(bv + col));
                    o.y = tanhf(v1 + __ldg(bv + col + 1));
                } else {
                    int j = col - 128;
                    o.x = sigmoidf_(v0 + __ldg(bu + j)) * __ldg(Ww + j);
                    o.y = sigmoidf_(v1 + __ldg(bu + j + 1)) * __ldg(Ww + j + 1);
                }
                *(float2*)&g_vu[(size_t)row * 256 + col] = o;
            }
        }
    }
}

// ---------------- score reduce: a[r] = sum_j t[j]*su[j] + bw ----------------
__global__ void k_score2(const float* __restrict__ bw)
{
    const int wid = threadIdx.x >> 5, lane = threadIdx.x & 31;
    const int row = blockIdx.x * 8 + wid;
    const float* p = g_vu + (size_t)row * 256;
    float s = 0.f;
#pragma unroll
    for (int t = 0; t < 4; t++) {
        int j = lane + 32 * t;
        s += p[j] * p[128 + j];
    }
#pragma unroll
    for (int o = 16; o > 0; o >>= 1) s += __shfl_xor_sync(0xffffffffu, s, o);
    if (lane == 0) g_a[row] = s + bw[0];
}

// ---------------- softmax over each group of 2048 ----------------
__global__ void k_softmax()
{
    __shared__ float red[256];
    float* p = g_a + (size_t)blockIdx.x * Mm;
    const int tid = threadIdx.x;
    float mx = -INFINITY;
    for (int i = tid; i < Mm; i += 256) mx = fmaxf(mx, p[i]);
    red[tid] = mx; __syncthreads();
    for (int s = 128; s > 0; s >>= 1) { if (tid < s) red[tid] = fmaxf(red[tid], red[tid + s]); __syncthreads(); }
    mx = red[0]; __syncthreads();
    float sum = 0.f;
    for (int i = tid; i < Mm; i += 256) { float e = expf(p[i] - mx); p[i] = e; sum += e; }
    red[tid] = sum; __syncthreads();
    for (int s = 128; s > 0; s >>= 1) { if (tid < s) red[tid] += red[tid + s]; __syncthreads(); }
    float inv = 1.f / red[0];
    for (int i = tid; i < Mm; i += 256) p[i] *= inv;
}

// ---------------- k_af: partial + reduce ----------------
__global__ void k_af_part()
{
    __shared__ float Asm[256];
    const int s = blockIdx.x, g = blockIdx.y;
    const int t = threadIdx.x;   // 256
    const size_t rowbase = (size_t)g * Mm + s * 256;
    Asm[t] = g_a[rowbase + t];
    __syncthreads();
    const uint32_t* pH = (const uint32_t*)g_midh;
    const uint32_t* pL = (const uint32_t*)g_midl;
    float a0 = 0.f, a1 = 0.f;
    for (int m = 0; m < 256; m++) {
        float w = Asm[m];
        size_t gi = (rowbase + m) * 256 + t;
        uint32_t h = pH[gi], l = pL[gi];
        float v0 = __uint_as_float(h << 16) + __uint_as_float(l << 16);
        float v1 = __uint_as_float(h & 0xffff0000u) + __uint_as_float(l & 0xffff0000u);
        a0 += w * v0;
        a1 += w * v1;
    }
    float* dst = g_afp + (size_t)(g * 8 + s) * Dd;
    dst[2 * t] = a0;
    dst[2 * t + 1] = a1;
}
__global__ void k_af_red()
{
    const int g = blockIdx.x, d = threadIdx.x;
    float s = 0.f;
    for (int p = 0; p < 8; p++) s += g_afp[(size_t)(g * 8 + p) * Dd + d];
    g_af[g * Dd + d] = s;
}

// ---------------- remaining small kernels ----------------
__global__ void k_subpreds(const float* __restrict__ Wsc, const float* __restrict__ bsc,
                           float* __restrict__ out)
{
    const int t = threadIdx.x;
    const int c = t & 1;
    const int rowcat = t >> 1;
    const int g = rowcat >> 3, b = rowcat & 7;
    const float* af = g_af + (size_t)(b * Gg + g) * Dd;
    float acc = bsc[c];
    for (int d = 0; d < Dd; d++) acc += af[d] * Wsc[d * Cc + c];
    out[16 + rowcat * Cc + c] = acc;
}

__global__ void k_a2(const float* __restrict__ Wv2, const float* __restrict__ bv2,
                     const float* __restrict__ Wu2, const float* __restrict__ bu2,
                     const float* __restrict__ Ww2, const float* __restrict__ bw2)
{
    __shared__ float red[DA];
    const int row = blockIdx.x;
    const int j = threadIdx.x;
    const float* af = g_af + (size_t)row * Dd;
    float dv = bv2[j], du = bu2[j];
    for (int d = 0; d < Dd; d++) {
        float a = af[d];
        dv += a * Wv2[d * DA + j];
        du += a * Wu2[d * DA + j];
    }
    red[j] = tanhf(dv) * sigmoidf_(du) * Ww2[j];
    __syncthreads();
    for (int s = 64; s > 0; s >>= 1) { if (j < s) red[j] += red[j + s]; __syncthreads(); }
    if (j == 0) g_a2[row] = red[0] + bw2[0];
}

__global__ void k_bag()
{
    const int b = blockIdx.x;
    const int d = threadIdx.x;
    float av[Gg];
    float mx = -INFINITY;
#pragma unroll
    for (int g = 0; g < Gg; g++) { av[g] = g_a2[b * Gg + g]; mx = fmaxf(mx, av[g]); }
    float s = 0.f;
#pragma unroll
    for (int g = 0; g < Gg; g++) { av[g] = expf(av[g] - mx); s += av[g]; }
    float inv = 1.f / s;
    float acc = 0.f;
#pragma unroll
    for (int g = 0; g < Gg; g++) acc += av[g] * inv * g_af[(size_t)(b * Gg + g) * Dd + d];
    g_bag[b * Dd + d] = acc;
}

__global__ void k_bagpred(const float* __restrict__ Wbc, const float* __restrict__ bbc,
                          float* __restrict__ out)
{
    const int t = threadIdx.x;
    const int b = t >> 1, c = t & 1;
    float acc = bbc[c];
    for (int d = 0; d < Dd; d++) acc += g_bag[b * Dd + d] * Wbc[d * Cc + c];
    out[t] = acc;
}

__global__ void k_xc(const float* __restrict__ rehearsal)
{
    const int i = blockIdx.x;
    for (int d = threadIdx.x; d < Dd; d += 256)
        g_xc[(size_t)i * Dd + d] = (i < Bq) ? g_bag[i * Dd + d] : rehearsal[(size_t)(i - Bq) * Dd + d];
}

__global__ void k_feat(const float* __restrict__ Wf, const float* __restrict__ bf)
{
    __shared__ float xs[Dd];
    __shared__ float red[DH];
    const int i = blockIdx.x;
    const int j = threadIdx.x;
    for (int d = j; d < Dd; d += DH) xs[d] = g_xc[(size_t)i * Dd + d];
    __syncthreads();
    float f = bf[j];
    for (int d = 0; d < Dd; d++) f += xs[d] * Wf[d * DH + j];
    f = (f >= 0.f) ? f : 0.01f * f;
    red[j] = f * f;
    __syncthreads();
    for (int s = 128; s > 0; s >>= 1) { if (j < s) red[j] += red[j + s]; __syncthreads(); }
    g_xn[(size_t)i * DH + j] = f / (sqrtf(red[0]) + 1e-12f);
}

__device__ __forceinline__ void topk_insert(float* bv, int* bi, float val, int id)
{
#pragma unroll
    for (int s = 0; s < Kk; s++) {
        if (val > bv[s] || (val == bv[s] && id < bi[s])) {
            for (int t = Kk - 1; t > s; t--) { bv[t] = bv[t - 1]; bi[t] = bi[t - 1]; }
            bv[s] = val; bi[s] = id;
            return;
        }
    }
}

__global__ void k_topk()
{
    __shared__ float xs[DH];
    __shared__ float sv[8][Kk];
    __shared__ int   si[8][Kk];
    const int i = blockIdx.x;
    const int tid = threadIdx.x;
    const int lane = tid & 31, w = tid >> 5;
    xs[tid] = g_xn[(size_t)i * DH + tid];
    __syncthreads();

    float bv[Kk]; int bi[Kk];
#pragma unroll
    for (int t = 0; t < Kk; t++) { bv[t] = -INFINITY; bi[t] = 0x7fffffff; }

    for (int j = w; j < NN; j += 8) {
        const float* xj = g_xn + (size_t)j * DH;
        float s = 0.f;
#pragma unroll
        for (int t = 0; t < 8; t++) s += xs[lane + 32 * t] * xj[lane + 32 * t];
#pragma unroll
        for (int o = 16; o > 0; o >>= 1) s += __shfl_xor_sync(0xffffffffu, s, o);
        if (lane == 0) topk_insert(bv, bi, s, j);
    }
    if (lane == 0) {
#pragma unroll
        for (int t = 0; t < Kk; t++) { sv[w][t] = bv[t]; si[w][t] = bi[t]; }
    }
    __syncthreads();
    if (tid == 0) {
        float fv[Kk]; int fi[Kk];
#pragma unroll
        for (int t = 0; t < Kk; t++) { fv[t] = -INFINITY; fi[t] = 0x7fffffff; }
        for (int w2 = 0; w2 < 8; w2++)
            for (int t = 0; t < Kk; t++) topk_insert(fv, fi, sv[w2][t], si[w2][t]);
        for (int t = 0; t < Kk; t++) g_idx[i * Kk + t] = fi[t];
    }
}

__global__ void k_h()
{
    const int i = blockIdx.x;
    const int d = threadIdx.x;
    const int i0 = g_idx[i * Kk + 0], i1 = g_idx[i * Kk + 1];
    const int i2 = g_idx[i * Kk + 2], i3 = g_idx[i * Kk + 3];
    float e = 0.25f * (g_xc[(size_t)i0 * Dd + d] + g_xc[(size_t)i1 * Dd + d] +
                       g_xc[(size_t)i2 * Dd + d] + g_xc[(size_t)i3 * Dd + d]);
    float pad = (i < Bq) ? g_bag[i * Dd + d] : 0.f;
    g_h[(size_t)i * Dd + d] = pad + e;
}

__global__ void k_m1()
{
    const int i = blockIdx.x;
    const int d = threadIdx.x;
    const int i0 = g_idx[i * Kk + 0], i1 = g_idx[i * Kk + 1];
    const int i2 = g_idx[i * Kk + 2], i3 = g_idx[i * Kk + 3];
    g_m1[(size_t)i * Dd + d] = 0.25f * (g_h[(size_t)i0 * Dd + d] + g_h[(size_t)i1 * Dd + d] +
                                        g_h[(size_t)i2 * Dd + d] + g_h[(size_t)i3 * Dd + d]);
}

__global__ void k_h1(const float* __restrict__ Wg1, const float* __restrict__ Wg1s,
                     const float* __restrict__ bg1)
{
    __shared__ float m1S[8][Dd];
    __shared__ float hS[8][Dd];
    const int rb = blockIdx.x * 8;
    const int j = threadIdx.x;
    for (int t = j; t < 8 * Dd; t += Dd) {
        int r = t >> 9, d = t & 511;
        m1S[r][d] = g_m1[(size_t)(rb + r) * Dd + d];
        hS[r][d]  = g_h[(size_t)(rb + r) * Dd + d];
    }
    __syncthreads();
    float acc[8];
    const float b0 = bg1[j];
#pragma unroll
    for (int r = 0; r < 8; r++) acc[r] = b0;
    for (int d = 0; d < Dd; d++) {
        float w1 = Wg1[(size_t)d * Dd + j];
        float ws = Wg1s[(size_t)d * Dd + j];
#pragma unroll
        for (int r = 0; r < 8; r++) acc[r] += m1S[r][d] * w1 + hS[r][d] * ws;
    }
#pragma unroll
    for (int r = 0; r < 8; r++)
        g_h1[(size_t)(rb + r) * Dd + j] = acc[r] > 0.f ? acc[r] : 0.f;
}

__global__ void k_logits(const float* __restrict__ Wg2, const float* __restrict__ Wg2s,
                         const float* __restrict__ bg2, float* __restrict__ out)
{
    __shared__ float r0[Dd];
    __shared__ float r1[Dd];
    const int i = blockIdx.x;
    const int d = threadIdx.x;
    const int i0 = g_idx[i * Kk + 0], i1 = g_idx[i * Kk + 1];
    const int i2 = g_idx[i * Kk + 2], i3 = g_idx[i * Kk + 3];
    float m2 = 0.25f * (g_h1[(size_t)i0 * Dd + d] + g_h1[(size_t)i1 * Dd + d] +
                        g_h1[(size_t)i2 * Dd + d] + g_h1[(size_t)i3 * Dd + d]);
    float hv = g_h1[(size_t)i * Dd + d];
    r0[d] = m2 * Wg2[d * Cc + 0] + hv * Wg2s[d * Cc + 0];
    r1[d] = m2 * Wg2[d * Cc + 1] + hv * Wg2s[d * Cc + 1];
    __syncthreads();
    for (int s = 256; s > 0; s >>= 1) {
        if (d < s) { r0[d] += r0[d + s]; r1[d] += r1[d + s]; }
        __syncthreads();
    }
    if (d == 0) {
        out[144 + i * Cc + 0] = r0[0] + bg2[0];
        out[144 + i * Cc + 1] = r1[0] + bg2[1];
    }
}

// ======================= launch =======================
extern "C" void kernel_launch(void* const* d_in, const int* in_sizes, int n_in,
                              void* d_out, int out_size)
{
    const float* x    = (const float*)d_in[0];
    const float* reh  = (const float*)d_in[1];
    const float* Wdr  = (const float*)d_in[2];
    const float* bdr  = (const float*)d_in[3];
    const float* Wv1  = (const float*)d_in[4];
    const float* bv1  = (const float*)d_in[5];
    const float* Wu1  = (const float*)d_in[6];
    const float* bu1  = (const float*)d_in[7];
    const float* Ww1  = (const float*)d_in[8];
    const float* bw1  = (const float*)d_in[9];
    const float* Wsc  = (const float*)d_in[10];
    const float* bsc  = (const float*)d_in[11];
    const float* Wv2  = (const float*)d_in[12];
    const float* bv2  = (const float*)d_in[13];
    const float* Wu2  = (const float*)d_in[14];
    const float* bu2  = (const float*)d_in[15];
    const float* Ww2  = (const float*)d_in[16];
    const float* bw2  = (const float*)d_in[17];
    const float* Wbc  = (const float*)d_in[18];
    const float* bbc  = (const float*)d_in[19];
    const float* Wf   = (const float*)d_in[20];
    const float* bf   = (const float*)d_in[21];
    const float* Wg1  = (const float*)d_in[22];
    const float* Wg1s = (const float*)d_in[23];
    const float* bg1  = (const float*)d_in[24];
    const float* Wg2  = (const float*)d_in[25];
    const float* Wg2s = (const float*)d_in[26];
    const float* bg2  = (const float*)d_in[27];
    float* out = (float*)d_out;

    k_prepWdr<<<1024, 256>>>(Wdr);
    k_prepWvu<<<512, 256>>>(Wv1, Wu1);
    k_gemm1<<<dim3(4, 1024), 256>>>(x, bdr);
    k_gemm2<<<dim3(2, 1024), 256>>>(bv1, bu1, Ww1);
    k_score2<<<RR / 8, 256>>>(bw1);
    k_softmax<<<NGRP, 256>>>();
    k_af_part<<<dim3(8, NGRP), 256>>>();
    k_af_red<<<NGRP, 512>>>();
    k_subpreds<<<1, 128>>>(Wsc, bsc, out);
    k_a2<<<NGRP, DA>>>(Wv2, bv2, Wu2, bu2, Ww2, bw2);
    k_bag<<<Bq, Dd>>>();
    k_bagpred<<<1, 16>>>(Wbc, bbc, out);
    k_xc<<<NN, 256>>>(reh);
    k_feat<<<NN, DH>>>(Wf, bf);
    k_topk<<<NN, 256>>>();
    k_h<<<NN, Dd>>>();
    k_m1<<<NN, Dd>>>();
    k_h1<<<NN / 8, Dd>>>(Wg1, Wg1s, bg1);
    k_logits<<<Bq, Dd>>>(Wg2, Wg2s, bg2, out);
}